// round 14
// baseline (speedup 1.0000x reference)
#include <cuda_runtime.h>
#include <cuda_bf16.h>
#include <cstdint>

#define NN 50000
#define HID 128
#define INDIM 16
#define OUTDIM 4
#define MAXE 600000
#define SCAN_CHUNK 1024
#define MAX_SCAN_BLOCKS 128
#define TSTRIDE 40   // smem tile row stride in bf16 elements (80B -> conflict-free ldmatrix)

// flat split-weight offsets (bf16 elems)
#define W2L_OFF 0
#define W2R_OFF 16384
#define W3L_OFF 32768
#define W3R_OFF 49152
#define W1L_OFF 65536
#define W1R_OFF 67584
#define WTOT    69632

// ---- scratch (static device globals; no runtime allocation) ----
__device__ float    g_agg16[NN * INDIM];   // layer-1 fp32 aggregation
__device__ uint32_t g_aggpk[NN * HID];     // packed (lo,hi) bf16 per col
__device__ float    g_hA[NN * HID];        // fp32 h (gather read path)
__device__ float    g_hB[NN * HID];
__device__ uint32_t g_hApk[NN * HID];      // packed h (GEMM staging path)
__device__ uint32_t g_hBpk[NN * HID];
__device__ __nv_bfloat16 g_wHi[WTOT];
__device__ __nv_bfloat16 g_wLo[WTOT];
__device__ int g_src[MAXE];
__device__ int g_dst[MAXE];
__device__ int g_csrc[MAXE];
__device__ int g_deg[NN];
__device__ int g_rowstart[NN + 1];
__device__ int g_cursor[NN];
__device__ int g_blocksum[MAX_SCAN_BLOCKS];
__device__ int g_is64;

// ================= helpers =================
__device__ __forceinline__ uint32_t smem_u32(const void* p) {
    uint32_t a;
    asm("{ .reg .u64 t; cvta.to.shared.u64 t, %1; cvt.u32.u64 %0, t; }" : "=r"(a) : "l"(p));
    return a;
}
__device__ __forceinline__ uint32_t prmt(uint32_t a, uint32_t b, uint32_t s) {
    uint32_t d;
    asm("prmt.b32 %0, %1, %2, %3;" : "=r"(d) : "r"(a), "r"(b), "r"(s));
    return d;
}

#define LDMX4(r, a)                                                            \
    asm volatile("ldmatrix.sync.aligned.m8n8.x4.shared.b16 {%0,%1,%2,%3}, [%4];" \
                 : "=r"((r)[0]), "=r"((r)[1]), "=r"((r)[2]), "=r"((r)[3])      \
                 : "r"(a))

__device__ __forceinline__ void mma16816(float* c, const uint32_t* a, const uint32_t* b) {
    asm volatile(
        "mma.sync.aligned.m16n8k16.row.col.f32.bf16.bf16.f32 "
        "{%0,%1,%2,%3}, {%4,%5,%6,%7}, {%8,%9}, {%0,%1,%2,%3};"
        : "+f"(c[0]), "+f"(c[1]), "+f"(c[2]), "+f"(c[3])
        : "r"(a[0]), "r"(a[1]), "r"(a[2]), "r"(a[3]), "r"(b[0]), "r"(b[1]));
}

__device__ __forceinline__ void split2(float v, __nv_bfloat16& hi, __nv_bfloat16& lo) {
    hi = __float2bfloat16(v);
    lo = __float2bfloat16(v - __bfloat162float(hi));
}
__device__ __forceinline__ uint32_t pack2(__nv_bfloat16 a, __nv_bfloat16 b) {
    __nv_bfloat162 t = __halves2bfloat162(a, b);
    return *reinterpret_cast<uint32_t*>(&t);
}
// packed col word: (lo, hi) with lo in low 16 bits
__device__ __forceinline__ uint32_t packcol(float v) {
    __nv_bfloat16 h, l;
    split2(v, h, l);
    return pack2(l, h);
}

// ================= CSR build (proven 170us form) =================
__global__ void init_kernel(const int* __restrict__ w, int M) {
    int i = blockIdx.x * blockDim.x + threadIdx.x;
    if (i < M) g_deg[i] = 0;
    if (blockIdx.x == 0) {
        __shared__ int anynz;
        if (threadIdx.x == 0) anynz = 0;
        __syncthreads();
        if (threadIdx.x < 64 && w[2 * threadIdx.x + 1] != 0) atomicOr(&anynz, 1);
        __syncthreads();
        if (threadIdx.x == 0) g_is64 = anynz ? 0 : 1;
    }
}

__global__ void convert_kernel(const int* __restrict__ w, int E) {
    int i = blockIdx.x * blockDim.x + threadIdx.x;
    if (i >= E) return;
    int s, d;
    if (g_is64) { s = w[2 * i]; d = w[2 * (E + i)]; }
    else        { s = w[i];     d = w[E + i];       }
    g_src[i] = s;
    g_dst[i] = d;
    atomicAdd(&g_deg[d], 1);
}

__device__ __forceinline__ void block_scan_1024(int& thread_sum, int& thread_excl, int* warp_buf) {
    int t = threadIdx.x;
    int lane = t & 31, w = t >> 5;
    int v = thread_sum;
#pragma unroll
    for (int off = 1; off < 32; off <<= 1) {
        int u = __shfl_up_sync(0xffffffffu, v, off);
        if (lane >= off) v += u;
    }
    if (lane == 31) warp_buf[w] = v;
    __syncthreads();
    if (w == 0) {
        int ws = (lane < 8) ? warp_buf[lane] : 0;
#pragma unroll
        for (int off = 1; off < 8; off <<= 1) {
            int u = __shfl_up_sync(0xffffffffu, ws, off);
            if (lane >= off) ws += u;
        }
        if (lane < 8) warp_buf[lane] = ws;
    }
    __syncthreads();
    thread_excl = v - thread_sum + (w > 0 ? warp_buf[w - 1] : 0);
}

__global__ void scan_phase1(int M) {
    __shared__ int warp_buf[8];
    int b = blockIdx.x, t = threadIdx.x;
    int base = b * SCAN_CHUNK + t * 4;
    int d[4] = {0, 0, 0, 0};
#pragma unroll
    for (int i = 0; i < 4; i++)
        if (base + i < M) d[i] = g_deg[base + i];
    int s = d[0] + d[1] + d[2] + d[3];
    int excl;
    block_scan_1024(s, excl, warp_buf);
    if (t == blockDim.x - 1) g_blocksum[b] = excl + s;
}

__global__ void scan_phase3(int M, int E, int NB) {
    __shared__ int warp_buf[8];
    __shared__ int bsum[MAX_SCAN_BLOCKS];
    __shared__ int boff;
    int b = blockIdx.x, t = threadIdx.x;
    if (t < NB) bsum[t] = g_blocksum[t];
    __syncthreads();
    if (t == 0) {
        int run = 0;
        for (int i = 0; i < b; i++) run += bsum[i];
        boff = run;
    }
    int base = b * SCAN_CHUNK + t * 4;
    int d[4] = {0, 0, 0, 0};
#pragma unroll
    for (int i = 0; i < 4; i++)
        if (base + i < M) d[i] = g_deg[base + i];
    int s = d[0] + d[1] + d[2] + d[3];
    int excl;
    block_scan_1024(s, excl, warp_buf);
    __syncthreads();
    int run = excl + boff;
#pragma unroll
    for (int i = 0; i < 4; i++) {
        if (base + i < M) {
            g_rowstart[base + i] = run;
            g_cursor[base + i] = run;
            run += d[i];
        }
    }
    if (b == 0 && t == 0) g_rowstart[M] = E;
}

__global__ void fill_kernel(int E) {
    int i = blockIdx.x * blockDim.x + threadIdx.x;
    if (i >= E) return;
    int d = g_dst[i];
    int pos = atomicAdd(&g_cursor[d], 1);
    g_csrc[pos] = g_src[i];
}

// ================= combined weight split (all 6 matrices) =================
__global__ void wsplit_all_kernel(const float* __restrict__ Wl2, const float* __restrict__ Wr2,
                                  const float* __restrict__ Wl3, const float* __restrict__ Wr3,
                                  const float* __restrict__ Wl1, const float* __restrict__ Wr1) {
    int i = blockIdx.x * blockDim.x + threadIdx.x;
    if (i >= WTOT) return;
    const float* src;
    int off;
    if (i < W2R_OFF)      { src = Wl2; off = i - W2L_OFF; }
    else if (i < W3L_OFF) { src = Wr2; off = i - W2R_OFF; }
    else if (i < W3R_OFF) { src = Wl3; off = i - W3L_OFF; }
    else if (i < W1L_OFF) { src = Wr3; off = i - W3R_OFF; }
    else if (i < W1R_OFF) { src = Wl1; off = i - W1L_OFF; }
    else                  { src = Wr1; off = i - W1R_OFF; }
    __nv_bfloat16 h, l;
    split2(src[off], h, l);
    g_wHi[i] = h;
    g_wLo[i] = l;
}

// ================= gathers =================
// Proven R9 read loop over fp32 h; output written packed (split only at store).
__global__ void gather128_kernel(const float* __restrict__ h, uint32_t* __restrict__ aggpk, int M) {
    int gt = blockIdx.x * blockDim.x + threadIdx.x;
    int n = gt >> 5;
    if (n >= M) return;
    int lane = gt & 31;
    int rs0 = g_rowstart[n], rs1 = g_rowstart[n + 1];
    float4 acc = make_float4(0.f, 0.f, 0.f, 0.f);
    int i = rs0;
    for (; i + 4 <= rs1; i += 4) {
        int s0 = g_csrc[i + 0];
        int s1 = g_csrc[i + 1];
        int s2 = g_csrc[i + 2];
        int s3 = g_csrc[i + 3];
        float4 v0 = __ldg(reinterpret_cast<const float4*>(h + (size_t)s0 * HID) + lane);
        float4 v1 = __ldg(reinterpret_cast<const float4*>(h + (size_t)s1 * HID) + lane);
        float4 v2 = __ldg(reinterpret_cast<const float4*>(h + (size_t)s2 * HID) + lane);
        float4 v3 = __ldg(reinterpret_cast<const float4*>(h + (size_t)s3 * HID) + lane);
        acc.x += v0.x + v1.x + v2.x + v3.x;
        acc.y += v0.y + v1.y + v2.y + v3.y;
        acc.z += v0.z + v1.z + v2.z + v3.z;
        acc.w += v0.w + v1.w + v2.w + v3.w;
    }
    for (; i < rs1; i++) {
        int s0 = g_csrc[i];
        float4 v0 = __ldg(reinterpret_cast<const float4*>(h + (size_t)s0 * HID) + lane);
        acc.x += v0.x; acc.y += v0.y; acc.z += v0.z; acc.w += v0.w;
    }
    float sc = 1.0f / (float)max(rs1 - rs0, 1);
    uint4 o;
    o.x = packcol(acc.x * sc);
    o.y = packcol(acc.y * sc);
    o.z = packcol(acc.z * sc);
    o.w = packcol(acc.w * sc);
    reinterpret_cast<uint4*>(aggpk + (size_t)n * HID)[lane] = o;
}

__global__ void gather16_kernel(const float* __restrict__ x, float* __restrict__ agg, int M) {
    int gt = blockIdx.x * blockDim.x + threadIdx.x;
    int n = gt >> 2;
    if (n >= M) return;
    int q = gt & 3;
    int rs0 = g_rowstart[n], rs1 = g_rowstart[n + 1];
    float4 acc = make_float4(0.f, 0.f, 0.f, 0.f);
    for (int i = rs0; i < rs1; i++) {
        int s0 = g_csrc[i];
        float4 v = __ldg(reinterpret_cast<const float4*>(x + (size_t)s0 * INDIM) + q);
        acc.x += v.x; acc.y += v.y; acc.z += v.z; acc.w += v.w;
    }
    float sc = 1.0f / (float)max(rs1 - rs0, 1);
    acc.x *= sc; acc.y *= sc; acc.z *= sc; acc.w *= sc;
    reinterpret_cast<float4*>(agg + (size_t)n * INDIM)[q] = acc;
}

// ================= layer-1 tensor GEMM (K=32) via mma.sync =================
// Dual-store epilogue: fp32 C (gather path) + packed Cpk (staging path).
__global__ void __launch_bounds__(256)
tensor_l1_kernel(const float* __restrict__ agg, const float* __restrict__ x,
                 const __nv_bfloat16* __restrict__ WHi, const __nv_bfloat16* __restrict__ WLo,
                 const float* __restrict__ bias, float* __restrict__ C,
                 uint32_t* __restrict__ Cpk, int M) {
    __shared__ __nv_bfloat16 sAhi[128 * TSTRIDE];
    __shared__ __nv_bfloat16 sAlo[128 * TSTRIDE];
    __shared__ __nv_bfloat16 sBhi[128 * TSTRIDE];
    __shared__ __nv_bfloat16 sBlo[128 * TSTRIDE];

    const int tid = threadIdx.x;
    const int wid = tid >> 5;
    const int lane = tid & 31;
    const int wm = wid & 3;
    const int wn = wid >> 2;
    const int m0 = blockIdx.x * 128;

    {
        int row = tid >> 1;
        int half = tid & 1;
        const float* src = half ? x : agg;
        int node = m0 + row;
        float4 v[4];
#pragma unroll
        for (int i = 0; i < 4; i++) v[i] = make_float4(0.f, 0.f, 0.f, 0.f);
        if (node < M) {
            const float4* p = reinterpret_cast<const float4*>(src + (size_t)node * INDIM);
#pragma unroll
            for (int i = 0; i < 4; i++) v[i] = p[i];
        }
        int so = row * TSTRIDE + half * 16;
#pragma unroll
        for (int i = 0; i < 4; i++) {
            __nv_bfloat16 h0, l0, h1, l1, h2, l2, h3, l3;
            split2(v[i].x, h0, l0);
            split2(v[i].y, h1, l1);
            split2(v[i].z, h2, l2);
            split2(v[i].w, h3, l3);
            uint2 ph, pl;
            ph.x = pack2(h0, h1); ph.y = pack2(h2, h3);
            pl.x = pack2(l0, l1); pl.y = pack2(l2, l3);
            *reinterpret_cast<uint2*>(sAhi + so + i * 4) = ph;
            *reinterpret_cast<uint2*>(sAlo + so + i * 4) = pl;
        }
    }
    {
        int row = tid >> 1;
        int half = tid & 1;
        const __nv_bfloat16* WH = WHi + half * 2048;
        const __nv_bfloat16* WL = WLo + half * 2048;
        int so = row * TSTRIDE + half * 16;
        uint4 h0 = *reinterpret_cast<const uint4*>(WH + row * 16);
        uint4 h1 = *reinterpret_cast<const uint4*>(WH + row * 16 + 8);
        uint4 l0 = *reinterpret_cast<const uint4*>(WL + row * 16);
        uint4 l1 = *reinterpret_cast<const uint4*>(WL + row * 16 + 8);
        *reinterpret_cast<uint4*>(sBhi + so) = h0;
        *reinterpret_cast<uint4*>(sBhi + so + 8) = h1;
        *reinterpret_cast<uint4*>(sBlo + so) = l0;
        *reinterpret_cast<uint4*>(sBlo + so + 8) = l1;
    }
    __syncthreads();

    const uint32_t uAhi = smem_u32(sAhi);
    const uint32_t uAlo = smem_u32(sAlo);
    const uint32_t uBhi = smem_u32(sBhi);
    const uint32_t uBlo = smem_u32(sBlo);

    float acc[2][8][4];
#pragma unroll
    for (int i = 0; i < 2; i++)
#pragma unroll
        for (int j = 0; j < 8; j++)
#pragma unroll
            for (int k = 0; k < 4; k++) acc[i][j][k] = 0.f;

    const int arow = wm * 32 + (lane & 15);
    const int akof = (lane & 16) ? 8 : 0;
    const int nrow0 = wn * 64 + (lane & 7) + ((lane & 16) ? 8 : 0);
    const int nkof = (lane & 8) ? 8 : 0;

#pragma unroll
    for (int ks = 0; ks < 2; ks++) {
        const int k0 = ks * 16;
        uint32_t ahi[2][4], alo[2][4];
#pragma unroll
        for (int mi = 0; mi < 2; mi++) {
            uint32_t off = ((arow + mi * 16) * TSTRIDE + k0 + akof) * 2;
            LDMX4(ahi[mi], uAhi + off);
            LDMX4(alo[mi], uAlo + off);
        }
#pragma unroll
        for (int np = 0; np < 4; np++) {
            uint32_t boff = ((nrow0 + np * 16) * TSTRIDE + k0 + nkof) * 2;
            uint32_t bh4[4], bl4[4];
            LDMX4(bh4, uBhi + boff);
            LDMX4(bl4, uBlo + boff);
#pragma unroll
            for (int mi = 0; mi < 2; mi++) {
#pragma unroll
                for (int na = 0; na < 2; na++) {
                    float* c = acc[mi][np * 2 + na];
                    mma16816(c, ahi[mi], &bh4[na * 2]);
                    mma16816(c, ahi[mi], &bl4[na * 2]);
                    mma16816(c, alo[mi], &bh4[na * 2]);
                }
            }
        }
    }

#pragma unroll
    for (int mi = 0; mi < 2; mi++) {
        int row0 = m0 + wm * 32 + mi * 16 + (lane >> 2);
        int row1 = row0 + 8;
#pragma unroll
        for (int ni = 0; ni < 8; ni++) {
            int col = wn * 64 + ni * 8 + 2 * (lane & 3);
            float b0 = __ldg(bias + col);
            float b1 = __ldg(bias + col + 1);
            float* c = acc[mi][ni];
            if (row0 < M) {
                float2 v;
                v.x = fmaxf(c[0] + b0, 0.f);
                v.y = fmaxf(c[1] + b1, 0.f);
                *reinterpret_cast<float2*>(C + (size_t)row0 * HID + col) = v;
                uint2 o;
                o.x = packcol(v.x);
                o.y = packcol(v.y);
                *reinterpret_cast<uint2*>(Cpk + (size_t)row0 * HID + col) = o;
            }
            if (row1 < M) {
                float2 v;
                v.x = fmaxf(c[2] + b0, 0.f);
                v.y = fmaxf(c[3] + b1, 0.f);
                *reinterpret_cast<float2*>(C + (size_t)row1 * HID + col) = v;
                uint2 o;
                o.x = packcol(v.x);
                o.y = packcol(v.y);
                *reinterpret_cast<uint2*>(Cpk + (size_t)row1 * HID + col) = o;
            }
        }
    }
}

// ================= tensor-core SAGE GEMM (layers 2/3), packed-A staging =================
template <bool FINAL>
__global__ void __launch_bounds__(256)
tensor_sage_kernel(const uint32_t* __restrict__ A0, const uint32_t* __restrict__ A1,
                   const __nv_bfloat16* __restrict__ W0hi, const __nv_bfloat16* __restrict__ W0lo,
                   const __nv_bfloat16* __restrict__ W1hi, const __nv_bfloat16* __restrict__ W1lo,
                   const float* __restrict__ bias, float* __restrict__ C,
                   uint32_t* __restrict__ Cpk,
                   const float* __restrict__ Wh, const float* __restrict__ bh,
                   float* __restrict__ out, int M) {
    __shared__ __nv_bfloat16 sAhi[128 * TSTRIDE];
    __shared__ __nv_bfloat16 sAlo[128 * TSTRIDE];
    __shared__ __nv_bfloat16 sBhi[128 * TSTRIDE];
    __shared__ __nv_bfloat16 sBlo[128 * TSTRIDE];
    __shared__ float sWh[OUTDIM * HID];
    __shared__ float sbh[OUTDIM];
    __shared__ float red[128 * 8];

    const int tid = threadIdx.x;
    const int wid = tid >> 5;
    const int lane = tid & 31;
    const int wm = wid & 3;
    const int wn = wid >> 2;
    const int m0 = blockIdx.x * 128;

    if (FINAL) {
        for (int u = tid; u < OUTDIM * HID; u += 256) sWh[u] = Wh[u];
        if (tid < OUTDIM) sbh[tid] = bh[tid];
    }

    const uint32_t uAhi = smem_u32(sAhi);
    const uint32_t uAlo = smem_u32(sAlo);
    const uint32_t uBhi = smem_u32(sBhi);
    const uint32_t uBlo = smem_u32(sBlo);

    float acc[2][8][4];
#pragma unroll
    for (int i = 0; i < 2; i++)
#pragma unroll
        for (int j = 0; j < 8; j++)
#pragma unroll
            for (int k = 0; k < 4; k++) acc[i][j][k] = 0.f;

    const int arow = wm * 32 + (lane & 15);
    const int akof = (lane & 16) ? 8 : 0;
    const int nrow0 = wn * 64 + (lane & 7) + ((lane & 16) ? 8 : 0);
    const int nkof = (lane & 8) ? 8 : 0;

#pragma unroll
    for (int chunk = 0; chunk < 8; chunk++) {
        const uint32_t* A = (chunk < 4) ? A0 : A1;
        const __nv_bfloat16* WH = (chunk < 4) ? W0hi : W1hi;
        const __nv_bfloat16* WL = (chunk < 4) ? W0lo : W1lo;
        const int koff = (chunk & 3) * 32;

        __syncthreads();
        // ---- stage A: packed words -> PRMT split into hi/lo tiles ----
#pragma unroll
        for (int i = 0; i < 4; i++) {
            int u = tid + i * 256;            // 1024 units of 4 cols
            int row = u >> 3;
            int q = (u & 7) * 4;
            uint4 w = make_uint4(0u, 0u, 0u, 0u);
            int node = m0 + row;
            if (node < M)
                w = *reinterpret_cast<const uint4*>(A + (size_t)node * HID + koff + q);
            uint2 ph, pl;
            ph.x = prmt(w.x, w.y, 0x7632u);   // hi pair (cols q, q+1)
            ph.y = prmt(w.z, w.w, 0x7632u);
            pl.x = prmt(w.x, w.y, 0x5410u);   // lo pair
            pl.y = prmt(w.z, w.w, 0x5410u);
            int so = row * TSTRIDE + q;
            *reinterpret_cast<uint2*>(sAhi + so) = ph;
            *reinterpret_cast<uint2*>(sAlo + so) = pl;
        }
        // ---- stage B (pre-split bf16) ----
#pragma unroll
        for (int i = 0; i < 2; i++) {
            int u = tid + i * 256;
            int row = u >> 2;
            int c = (u & 3) * 8;
            uint4 vh = *reinterpret_cast<const uint4*>(WH + (size_t)row * HID + koff + c);
            uint4 vl = *reinterpret_cast<const uint4*>(WL + (size_t)row * HID + koff + c);
            int so = row * TSTRIDE + c;
            *reinterpret_cast<uint4*>(sBhi + so) = vh;
            *reinterpret_cast<uint4*>(sBlo + so) = vl;
        }
        __syncthreads();

#pragma unroll
        for (int ks = 0; ks < 2; ks++) {
            const int k0 = ks * 16;
            uint32_t ahi[2][4], alo[2][4];
#pragma unroll
            for (int mi = 0; mi < 2; mi++) {
                uint32_t off = ((arow + mi * 16) * TSTRIDE + k0 + akof) * 2;
                LDMX4(ahi[mi], uAhi + off);
                LDMX4(alo[mi], uAlo + off);
            }
#pragma unroll
            for (int np = 0; np < 4; np++) {
                uint32_t boff = ((nrow0 + np * 16) * TSTRIDE + k0 + nkof) * 2;
                uint32_t bh4[4], bl4[4];
                LDMX4(bh4, uBhi + boff);
                LDMX4(bl4, uBlo + boff);
#pragma unroll
                for (int mi = 0; mi < 2; mi++) {
#pragma unroll
                    for (int na = 0; na < 2; na++) {
                        float* c = acc[mi][np * 2 + na];
                        mma16816(c, ahi[mi], &bh4[na * 2]);
                        mma16816(c, ahi[mi], &bl4[na * 2]);
                        mma16816(c, alo[mi], &bh4[na * 2]);
                    }
                }
            }
        }
    }

    if (!FINAL) {
        // dual-store epilogue: fp32 (gather path) + packed (staging path)
#pragma unroll
        for (int mi = 0; mi < 2; mi++) {
            int row0 = m0 + wm * 32 + mi * 16 + (lane >> 2);
            int row1 = row0 + 8;
#pragma unroll
            for (int ni = 0; ni < 8; ni++) {
                int col = wn * 64 + ni * 8 + 2 * (lane & 3);
                float b0 = __ldg(bias + col);
                float b1 = __ldg(bias + col + 1);
                float* c = acc[mi][ni];
                if (row0 < M) {
                    float2 v;
                    v.x = fmaxf(c[0] + b0, 0.f);
                    v.y = fmaxf(c[1] + b1, 0.f);
                    *reinterpret_cast<float2*>(C + (size_t)row0 * HID + col) = v;
                    uint2 o;
                    o.x = packcol(v.x);
                    o.y = packcol(v.y);
                    *reinterpret_cast<uint2*>(Cpk + (size_t)row0 * HID + col) = o;
                }
                if (row1 < M) {
                    float2 v;
                    v.x = fmaxf(c[2] + b0, 0.f);
                    v.y = fmaxf(c[3] + b1, 0.f);
                    *reinterpret_cast<float2*>(C + (size_t)row1 * HID + col) = v;
                    uint2 o;
                    o.x = packcol(v.x);
                    o.y = packcol(v.y);
                    *reinterpret_cast<uint2*>(Cpk + (size_t)row1 * HID + col) = o;
                }
            }
        }
    } else {
#pragma unroll
        for (int mi = 0; mi < 2; mi++) {
            float p0[OUTDIM] = {0.f, 0.f, 0.f, 0.f};
            float p1[OUTDIM] = {0.f, 0.f, 0.f, 0.f};
#pragma unroll
            for (int ni = 0; ni < 8; ni++) {
                int col = wn * 64 + ni * 8 + 2 * (lane & 3);
                float b0 = __ldg(bias + col);
                float b1 = __ldg(bias + col + 1);
                float* c = acc[mi][ni];
                float v0 = fmaxf(c[0] + b0, 0.f);
                float v1 = fmaxf(c[1] + b1, 0.f);
                float v2 = fmaxf(c[2] + b0, 0.f);
                float v3 = fmaxf(c[3] + b1, 0.f);
#pragma unroll
                for (int j = 0; j < OUTDIM; j++) {
                    float w0 = sWh[j * HID + col];
                    float w1 = sWh[j * HID + col + 1];
                    p0[j] += v0 * w0 + v1 * w1;
                    p1[j] += v2 * w0 + v3 * w1;
                }
            }
#pragma unroll
            for (int j = 0; j < OUTDIM; j++) {
                p0[j] += __shfl_xor_sync(0xffffffffu, p0[j], 1);
                p0[j] += __shfl_xor_sync(0xffffffffu, p0[j], 2);
                p1[j] += __shfl_xor_sync(0xffffffffu, p1[j], 1);
                p1[j] += __shfl_xor_sync(0xffffffffu, p1[j], 2);
            }
            if ((lane & 3) == 0) {
                int r0 = wm * 32 + mi * 16 + (lane >> 2);
                int r1 = r0 + 8;
#pragma unroll
                for (int j = 0; j < OUTDIM; j++) {
                    red[r0 * 8 + j * 2 + wn] = p0[j];
                    red[r1 * 8 + j * 2 + wn] = p1[j];
                }
            }
        }
        __syncthreads();
        for (int u = tid; u < 128 * OUTDIM; u += 256) {
            int row = u >> 2;
            int j = u & 3;
            int node = m0 + row;
            if (node < M)
                out[(size_t)node * OUTDIM + j] =
                    red[row * 8 + j * 2 + 0] + red[row * 8 + j * 2 + 1] + sbh[j];
        }
    }
}

// ---------------------------------------------------------------
extern "C" void kernel_launch(void* const* d_in, const int* in_sizes, int n_in,
                              void* d_out, int out_size) {
    (void)n_in; (void)out_size;
    const float* x   = (const float*)d_in[0];
    const int*   ei  = (const int*)d_in[1];
    const float* Wl1 = (const float*)d_in[2];
    const float* Wr1 = (const float*)d_in[3];
    const float* b1  = (const float*)d_in[4];
    const float* Wl2 = (const float*)d_in[5];
    const float* Wr2 = (const float*)d_in[6];
    const float* b2  = (const float*)d_in[7];
    const float* Wl3 = (const float*)d_in[8];
    const float* Wr3 = (const float*)d_in[9];
    const float* b3  = (const float*)d_in[10];
    const float* Wh  = (const float*)d_in[11];
    const float* bh  = (const float*)d_in[12];
    float* out = (float*)d_out;

    const int M = in_sizes[0] / INDIM;   // 50000
    const int E = in_sizes[1] / 2;       // 600000

    float *agg16, *hA, *hB;
    uint32_t *aggpk, *hApk, *hBpk;
    __nv_bfloat16 *wHi, *wLo;
    cudaGetSymbolAddress((void**)&agg16, g_agg16);
    cudaGetSymbolAddress((void**)&aggpk, g_aggpk);
    cudaGetSymbolAddress((void**)&hA, g_hA);
    cudaGetSymbolAddress((void**)&hB, g_hB);
    cudaGetSymbolAddress((void**)&hApk, g_hApk);
    cudaGetSymbolAddress((void**)&hBpk, g_hBpk);
    cudaGetSymbolAddress((void**)&wHi, g_wHi);
    cudaGetSymbolAddress((void**)&wLo, g_wLo);

    const int T = 256;
    const int NB = (M + SCAN_CHUNK - 1) / SCAN_CHUNK;

    // ---- CSR build (proven 170us path) ----
    init_kernel<<<(M + T - 1) / T, T>>>(ei, M);
    convert_kernel<<<(E + T - 1) / T, T>>>(ei, E);
    scan_phase1<<<NB, 256>>>(M);
    scan_phase3<<<NB, 256>>>(M, E, NB);
    fill_kernel<<<(E + T - 1) / T, T>>>(E);

    // ---- weight splits (all 6 in one launch) ----
    wsplit_all_kernel<<<(WTOT + T - 1) / T, T>>>(Wl2, Wr2, Wl3, Wr3, Wl1, Wr1);

    const int gemmBlocks = (M + 127) / 128;

    // ---- layer 1 (16 -> 128), mma.sync, dual-store output ----
    gather16_kernel<<<((M * 4) + T - 1) / T, T>>>(x, agg16, M);
    tensor_l1_kernel<<<gemmBlocks, 256>>>(agg16, x, wHi + W1L_OFF, wLo + W1L_OFF, b1, hA, hApk, M);

    // ---- layer 2 (128 -> 128) ----
    gather128_kernel<<<((M * 32) + T - 1) / T, T>>>(hA, aggpk, M);
    tensor_sage_kernel<false><<<gemmBlocks, 256>>>(aggpk, hApk,
        wHi + W2L_OFF, wLo + W2L_OFF, wHi + W2R_OFF, wLo + W2R_OFF,
        b2, hB, hBpk, nullptr, nullptr, nullptr, M);

    // ---- layer 3 (128 -> 128) + fused final projection ----
    gather128_kernel<<<((M * 32) + T - 1) / T, T>>>(hB, aggpk, M);
    tensor_sage_kernel<true><<<gemmBlocks, 256>>>(aggpk, hBpk,
        wHi + W3L_OFF, wLo + W3L_OFF, wHi + W3R_OFF, wLo + W3R_OFF,
        b3, nullptr, nullptr, Wh, bh, out, M);
}

// round 15
// speedup vs baseline: 1.0541x; 1.0541x over previous
#include <cuda_runtime.h>
#include <cuda_bf16.h>
#include <cstdint>

#define NN 50000
#define HID 128
#define INDIM 16
#define OUTDIM 4
#define MAXE 600000
#define SCAN_CHUNK 1024
#define MAX_SCAN_BLOCKS 128
#define TSTRIDE 40   // smem tile row stride in bf16 elements (80B -> conflict-free ldmatrix)

// flat split-weight offsets (bf16 elems)
#define W2L_OFF 0
#define W2R_OFF 16384
#define W3L_OFF 32768
#define W3R_OFF 49152
#define W1L_OFF 65536
#define W1R_OFF 67584
#define WTOT    69632

// ---- scratch (static device globals; no runtime allocation) ----
__device__ float g_agg[NN * HID];
__device__ float g_hA[NN * HID];
__device__ float g_hB[NN * HID];
__device__ __nv_bfloat16 g_wHi[WTOT];
__device__ __nv_bfloat16 g_wLo[WTOT];
__device__ int g_src[MAXE];
__device__ int g_dst[MAXE];
__device__ int g_csrc[MAXE];
__device__ int g_deg[NN];
__device__ int g_rowstart[NN + 1];
__device__ int g_cursor[NN];
__device__ int g_blocksum[MAX_SCAN_BLOCKS];
__device__ int g_is64;

// ================= helpers =================
__device__ __forceinline__ uint32_t smem_u32(const void* p) {
    uint32_t a;
    asm("{ .reg .u64 t; cvta.to.shared.u64 t, %1; cvt.u32.u64 %0, t; }" : "=r"(a) : "l"(p));
    return a;
}

#define LDMX4(r, a)                                                            \
    asm volatile("ldmatrix.sync.aligned.m8n8.x4.shared.b16 {%0,%1,%2,%3}, [%4];" \
                 : "=r"((r)[0]), "=r"((r)[1]), "=r"((r)[2]), "=r"((r)[3])      \
                 : "r"(a))

__device__ __forceinline__ void mma16816(float* c, const uint32_t* a, const uint32_t* b) {
    asm volatile(
        "mma.sync.aligned.m16n8k16.row.col.f32.bf16.bf16.f32 "
        "{%0,%1,%2,%3}, {%4,%5,%6,%7}, {%8,%9}, {%0,%1,%2,%3};"
        : "+f"(c[0]), "+f"(c[1]), "+f"(c[2]), "+f"(c[3])
        : "r"(a[0]), "r"(a[1]), "r"(a[2]), "r"(a[3]), "r"(b[0]), "r"(b[1]));
}

__device__ __forceinline__ void split2(float v, __nv_bfloat16& hi, __nv_bfloat16& lo) {
    hi = __float2bfloat16(v);
    lo = __float2bfloat16(v - __bfloat162float(hi));
}
__device__ __forceinline__ uint32_t pack2(__nv_bfloat16 a, __nv_bfloat16 b) {
    __nv_bfloat162 t = __halves2bfloat162(a, b);
    return *reinterpret_cast<uint32_t*>(&t);
}

// ================= CSR build (proven 170us form) =================
__global__ void init_kernel(const int* __restrict__ w, int M) {
    int i = blockIdx.x * blockDim.x + threadIdx.x;
    if (i < M) g_deg[i] = 0;
    if (blockIdx.x == 0) {
        __shared__ int anynz;
        if (threadIdx.x == 0) anynz = 0;
        __syncthreads();
        if (threadIdx.x < 64 && w[2 * threadIdx.x + 1] != 0) atomicOr(&anynz, 1);
        __syncthreads();
        if (threadIdx.x == 0) g_is64 = anynz ? 0 : 1;
    }
}

__global__ void convert_kernel(const int* __restrict__ w, int E) {
    int i = blockIdx.x * blockDim.x + threadIdx.x;
    if (i >= E) return;
    int s, d;
    if (g_is64) { s = w[2 * i]; d = w[2 * (E + i)]; }
    else        { s = w[i];     d = w[E + i];       }
    g_src[i] = s;
    g_dst[i] = d;
    atomicAdd(&g_deg[d], 1);
}

__device__ __forceinline__ void block_scan_1024(int& thread_sum, int& thread_excl, int* warp_buf) {
    int t = threadIdx.x;
    int lane = t & 31, w = t >> 5;
    int v = thread_sum;
#pragma unroll
    for (int off = 1; off < 32; off <<= 1) {
        int u = __shfl_up_sync(0xffffffffu, v, off);
        if (lane >= off) v += u;
    }
    if (lane == 31) warp_buf[w] = v;
    __syncthreads();
    if (w == 0) {
        int ws = (lane < 8) ? warp_buf[lane] : 0;
#pragma unroll
        for (int off = 1; off < 8; off <<= 1) {
            int u = __shfl_up_sync(0xffffffffu, ws, off);
            if (lane >= off) ws += u;
        }
        if (lane < 8) warp_buf[lane] = ws;
    }
    __syncthreads();
    thread_excl = v - thread_sum + (w > 0 ? warp_buf[w - 1] : 0);
}

__global__ void scan_phase1(int M) {
    __shared__ int warp_buf[8];
    int b = blockIdx.x, t = threadIdx.x;
    int base = b * SCAN_CHUNK + t * 4;
    int d[4] = {0, 0, 0, 0};
#pragma unroll
    for (int i = 0; i < 4; i++)
        if (base + i < M) d[i] = g_deg[base + i];
    int s = d[0] + d[1] + d[2] + d[3];
    int excl;
    block_scan_1024(s, excl, warp_buf);
    if (t == blockDim.x - 1) g_blocksum[b] = excl + s;
}

__global__ void scan_phase3(int M, int E, int NB) {
    __shared__ int warp_buf[8];
    __shared__ int bsum[MAX_SCAN_BLOCKS];
    __shared__ int boff;
    int b = blockIdx.x, t = threadIdx.x;
    if (t < NB) bsum[t] = g_blocksum[t];
    __syncthreads();
    if (t == 0) {
        int run = 0;
        for (int i = 0; i < b; i++) run += bsum[i];
        boff = run;
    }
    int base = b * SCAN_CHUNK + t * 4;
    int d[4] = {0, 0, 0, 0};
#pragma unroll
    for (int i = 0; i < 4; i++)
        if (base + i < M) d[i] = g_deg[base + i];
    int s = d[0] + d[1] + d[2] + d[3];
    int excl;
    block_scan_1024(s, excl, warp_buf);
    __syncthreads();
    int run = excl + boff;
#pragma unroll
    for (int i = 0; i < 4; i++) {
        if (base + i < M) {
            g_rowstart[base + i] = run;
            g_cursor[base + i] = run;
            run += d[i];
        }
    }
    if (b == 0 && t == 0) g_rowstart[M] = E;
}

__global__ void fill_kernel(int E) {
    int i = blockIdx.x * blockDim.x + threadIdx.x;
    if (i >= E) return;
    int d = g_dst[i];
    int pos = atomicAdd(&g_cursor[d], 1);
    g_csrc[pos] = g_src[i];
}

// ================= combined weight split (all 6 matrices) =================
__global__ void wsplit_all_kernel(const float* __restrict__ Wl2, const float* __restrict__ Wr2,
                                  const float* __restrict__ Wl3, const float* __restrict__ Wr3,
                                  const float* __restrict__ Wl1, const float* __restrict__ Wr1) {
    int i = blockIdx.x * blockDim.x + threadIdx.x;
    if (i >= WTOT) return;
    const float* src;
    int off;
    if (i < W2R_OFF)      { src = Wl2; off = i - W2L_OFF; }
    else if (i < W3L_OFF) { src = Wr2; off = i - W2R_OFF; }
    else if (i < W3R_OFF) { src = Wl3; off = i - W3L_OFF; }
    else if (i < W1L_OFF) { src = Wr3; off = i - W3R_OFF; }
    else if (i < W1R_OFF) { src = Wl1; off = i - W1L_OFF; }
    else                  { src = Wr1; off = i - W1R_OFF; }
    __nv_bfloat16 h, l;
    split2(src[off], h, l);
    g_wHi[i] = h;
    g_wLo[i] = l;
}

// ================= gathers (fp32, CSR) — proven R9 form =================
__global__ void gather128_kernel(const float* __restrict__ h, float* __restrict__ agg, int M) {
    int gt = blockIdx.x * blockDim.x + threadIdx.x;
    int n = gt >> 5;
    if (n >= M) return;
    int lane = gt & 31;
    int rs0 = g_rowstart[n], rs1 = g_rowstart[n + 1];
    float4 acc = make_float4(0.f, 0.f, 0.f, 0.f);
    int i = rs0;
    for (; i + 4 <= rs1; i += 4) {
        int s0 = g_csrc[i + 0];
        int s1 = g_csrc[i + 1];
        int s2 = g_csrc[i + 2];
        int s3 = g_csrc[i + 3];
        float4 v0 = __ldg(reinterpret_cast<const float4*>(h + (size_t)s0 * HID) + lane);
        float4 v1 = __ldg(reinterpret_cast<const float4*>(h + (size_t)s1 * HID) + lane);
        float4 v2 = __ldg(reinterpret_cast<const float4*>(h + (size_t)s2 * HID) + lane);
        float4 v3 = __ldg(reinterpret_cast<const float4*>(h + (size_t)s3 * HID) + lane);
        acc.x += v0.x + v1.x + v2.x + v3.x;
        acc.y += v0.y + v1.y + v2.y + v3.y;
        acc.z += v0.z + v1.z + v2.z + v3.z;
        acc.w += v0.w + v1.w + v2.w + v3.w;
    }
    for (; i < rs1; i++) {
        int s0 = g_csrc[i];
        float4 v0 = __ldg(reinterpret_cast<const float4*>(h + (size_t)s0 * HID) + lane);
        acc.x += v0.x; acc.y += v0.y; acc.z += v0.z; acc.w += v0.w;
    }
    float sc = 1.0f / (float)max(rs1 - rs0, 1);
    acc.x *= sc; acc.y *= sc; acc.z *= sc; acc.w *= sc;
    reinterpret_cast<float4*>(agg + (size_t)n * HID)[lane] = acc;
}

__global__ void gather16_kernel(const float* __restrict__ x, float* __restrict__ agg, int M) {
    int gt = blockIdx.x * blockDim.x + threadIdx.x;
    int n = gt >> 2;
    if (n >= M) return;
    int q = gt & 3;
    int rs0 = g_rowstart[n], rs1 = g_rowstart[n + 1];
    float4 acc = make_float4(0.f, 0.f, 0.f, 0.f);
    for (int i = rs0; i < rs1; i++) {
        int s0 = g_csrc[i];
        float4 v = __ldg(reinterpret_cast<const float4*>(x + (size_t)s0 * INDIM) + q);
        acc.x += v.x; acc.y += v.y; acc.z += v.z; acc.w += v.w;
    }
    float sc = 1.0f / (float)max(rs1 - rs0, 1);
    acc.x *= sc; acc.y *= sc; acc.z *= sc; acc.w *= sc;
    reinterpret_cast<float4*>(agg + (size_t)n * INDIM)[q] = acc;
}

// ================= layer-1 tensor GEMM (K=32) via mma.sync =================
__global__ void __launch_bounds__(256)
tensor_l1_kernel(const float* __restrict__ agg, const float* __restrict__ x,
                 const __nv_bfloat16* __restrict__ WHi, const __nv_bfloat16* __restrict__ WLo,
                 const float* __restrict__ bias, float* __restrict__ C, int M) {
    __shared__ __nv_bfloat16 sAhi[128 * TSTRIDE];
    __shared__ __nv_bfloat16 sAlo[128 * TSTRIDE];
    __shared__ __nv_bfloat16 sBhi[128 * TSTRIDE];
    __shared__ __nv_bfloat16 sBlo[128 * TSTRIDE];

    const int tid = threadIdx.x;
    const int wid = tid >> 5;
    const int lane = tid & 31;
    const int wm = wid & 3;
    const int wn = wid >> 2;
    const int m0 = blockIdx.x * 128;

    {
        int row = tid >> 1;
        int half = tid & 1;
        const float* src = half ? x : agg;
        int node = m0 + row;
        float4 v[4];
#pragma unroll
        for (int i = 0; i < 4; i++) v[i] = make_float4(0.f, 0.f, 0.f, 0.f);
        if (node < M) {
            const float4* p = reinterpret_cast<const float4*>(src + (size_t)node * INDIM);
#pragma unroll
            for (int i = 0; i < 4; i++) v[i] = p[i];
        }
        int so = row * TSTRIDE + half * 16;
#pragma unroll
        for (int i = 0; i < 4; i++) {
            __nv_bfloat16 h0, l0, h1, l1, h2, l2, h3, l3;
            split2(v[i].x, h0, l0);
            split2(v[i].y, h1, l1);
            split2(v[i].z, h2, l2);
            split2(v[i].w, h3, l3);
            uint2 ph, pl;
            ph.x = pack2(h0, h1); ph.y = pack2(h2, h3);
            pl.x = pack2(l0, l1); pl.y = pack2(l2, l3);
            *reinterpret_cast<uint2*>(sAhi + so + i * 4) = ph;
            *reinterpret_cast<uint2*>(sAlo + so + i * 4) = pl;
        }
    }
    {
        int row = tid >> 1;
        int half = tid & 1;
        const __nv_bfloat16* WH = WHi + half * 2048;
        const __nv_bfloat16* WL = WLo + half * 2048;
        int so = row * TSTRIDE + half * 16;
        uint4 h0 = *reinterpret_cast<const uint4*>(WH + row * 16);
        uint4 h1 = *reinterpret_cast<const uint4*>(WH + row * 16 + 8);
        uint4 l0 = *reinterpret_cast<const uint4*>(WL + row * 16);
        uint4 l1 = *reinterpret_cast<const uint4*>(WL + row * 16 + 8);
        *reinterpret_cast<uint4*>(sBhi + so) = h0;
        *reinterpret_cast<uint4*>(sBhi + so + 8) = h1;
        *reinterpret_cast<uint4*>(sBlo + so) = l0;
        *reinterpret_cast<uint4*>(sBlo + so + 8) = l1;
    }
    __syncthreads();

    const uint32_t uAhi = smem_u32(sAhi);
    const uint32_t uAlo = smem_u32(sAlo);
    const uint32_t uBhi = smem_u32(sBhi);
    const uint32_t uBlo = smem_u32(sBlo);

    float acc[2][8][4];
#pragma unroll
    for (int i = 0; i < 2; i++)
#pragma unroll
        for (int j = 0; j < 8; j++)
#pragma unroll
            for (int k = 0; k < 4; k++) acc[i][j][k] = 0.f;

    const int arow = wm * 32 + (lane & 15);
    const int akof = (lane & 16) ? 8 : 0;
    const int nrow0 = wn * 64 + (lane & 7) + ((lane & 16) ? 8 : 0);
    const int nkof = (lane & 8) ? 8 : 0;

#pragma unroll
    for (int ks = 0; ks < 2; ks++) {
        const int k0 = ks * 16;
        uint32_t ahi[2][4], alo[2][4];
#pragma unroll
        for (int mi = 0; mi < 2; mi++) {
            uint32_t off = ((arow + mi * 16) * TSTRIDE + k0 + akof) * 2;
            LDMX4(ahi[mi], uAhi + off);
            LDMX4(alo[mi], uAlo + off);
        }
#pragma unroll
        for (int np = 0; np < 4; np++) {
            uint32_t boff = ((nrow0 + np * 16) * TSTRIDE + k0 + nkof) * 2;
            uint32_t bh4[4], bl4[4];
            LDMX4(bh4, uBhi + boff);
            LDMX4(bl4, uBlo + boff);
#pragma unroll
            for (int mi = 0; mi < 2; mi++) {
#pragma unroll
                for (int na = 0; na < 2; na++) {
                    float* c = acc[mi][np * 2 + na];
                    mma16816(c, ahi[mi], &bh4[na * 2]);
                    mma16816(c, ahi[mi], &bl4[na * 2]);
                    mma16816(c, alo[mi], &bh4[na * 2]);
                }
            }
        }
    }

#pragma unroll
    for (int mi = 0; mi < 2; mi++) {
        int row0 = m0 + wm * 32 + mi * 16 + (lane >> 2);
        int row1 = row0 + 8;
#pragma unroll
        for (int ni = 0; ni < 8; ni++) {
            int col = wn * 64 + ni * 8 + 2 * (lane & 3);
            float b0 = __ldg(bias + col);
            float b1 = __ldg(bias + col + 1);
            float* c = acc[mi][ni];
            if (row0 < M) {
                float2 v;
                v.x = fmaxf(c[0] + b0, 0.f);
                v.y = fmaxf(c[1] + b1, 0.f);
                *reinterpret_cast<float2*>(C + (size_t)row0 * HID + col) = v;
            }
            if (row1 < M) {
                float2 v;
                v.x = fmaxf(c[2] + b0, 0.f);
                v.y = fmaxf(c[3] + b1, 0.f);
                *reinterpret_cast<float2*>(C + (size_t)row1 * HID + col) = v;
            }
        }
    }
}

// ================= tensor-core SAGE GEMM (layers 2/3) via mma.sync =================
// Software-pipelined: next chunk's A tile is prefetched into registers while
// the current chunk's MMAs run, hiding the exposed global-load latency.
template <bool FINAL>
__global__ void __launch_bounds__(256, 2)
tensor_sage_kernel(const float* __restrict__ A0, const float* __restrict__ A1,
                   const __nv_bfloat16* __restrict__ W0hi, const __nv_bfloat16* __restrict__ W0lo,
                   const __nv_bfloat16* __restrict__ W1hi, const __nv_bfloat16* __restrict__ W1lo,
                   const float* __restrict__ bias, float* __restrict__ C,
                   const float* __restrict__ Wh, const float* __restrict__ bh,
                   float* __restrict__ out, int M) {
    __shared__ __nv_bfloat16 sAhi[128 * TSTRIDE];
    __shared__ __nv_bfloat16 sAlo[128 * TSTRIDE];
    __shared__ __nv_bfloat16 sBhi[128 * TSTRIDE];
    __shared__ __nv_bfloat16 sBlo[128 * TSTRIDE];
    __shared__ float sWh[OUTDIM * HID];
    __shared__ float sbh[OUTDIM];
    __shared__ float red[128 * 8];

    const int tid = threadIdx.x;
    const int wid = tid >> 5;
    const int lane = tid & 31;
    const int wm = wid & 3;
    const int wn = wid >> 2;
    const int m0 = blockIdx.x * 128;

    if (FINAL) {
        for (int u = tid; u < OUTDIM * HID; u += 256) sWh[u] = Wh[u];
        if (tid < OUTDIM) sbh[tid] = bh[tid];
    }

    const uint32_t uAhi = smem_u32(sAhi);
    const uint32_t uAlo = smem_u32(sAlo);
    const uint32_t uBhi = smem_u32(sBhi);
    const uint32_t uBlo = smem_u32(sBlo);

    float acc[2][8][4];
#pragma unroll
    for (int i = 0; i < 2; i++)
#pragma unroll
        for (int j = 0; j < 8; j++)
#pragma unroll
            for (int k = 0; k < 4; k++) acc[i][j][k] = 0.f;

    const int arow = wm * 32 + (lane & 15);
    const int akof = (lane & 16) ? 8 : 0;
    const int nrow0 = wn * 64 + (lane & 7) + ((lane & 16) ? 8 : 0);
    const int nkof = (lane & 8) ? 8 : 0;

    // A prefetch registers + per-thread staging coords
    const int prow = tid >> 3;             // 0..31 base row (x4 units step 32 rows? no: u>>3)
    float4 pf[4];
    auto fetchA = [&](int chunk) {
        const float* A = (chunk < 4) ? A0 : A1;
        const int koff = (chunk & 3) * 32;
#pragma unroll
        for (int i = 0; i < 4; i++) {
            int u = tid + i * 256;
            int row = u >> 3;
            int q = (u & 7) * 4;
            pf[i] = make_float4(0.f, 0.f, 0.f, 0.f);
            int node = m0 + row;
            if (node < M)
                pf[i] = *reinterpret_cast<const float4*>(A + (size_t)node * HID + koff + q);
        }
    };
    (void)prow;

    fetchA(0);
#pragma unroll
    for (int chunk = 0; chunk < 8; chunk++) {
        const __nv_bfloat16* WH = (chunk < 4) ? W0hi : W1hi;
        const __nv_bfloat16* WL = (chunk < 4) ? W0lo : W1lo;
        const int koff = (chunk & 3) * 32;

        // ---- stage A from prefetch registers (smem free: sync at loop tail) ----
#pragma unroll
        for (int i = 0; i < 4; i++) {
            int u = tid + i * 256;
            int row = u >> 3;
            int q = (u & 7) * 4;
            __nv_bfloat16 h0, l0, h1, l1, h2, l2, h3, l3;
            split2(pf[i].x, h0, l0);
            split2(pf[i].y, h1, l1);
            split2(pf[i].z, h2, l2);
            split2(pf[i].w, h3, l3);
            int so = row * TSTRIDE + q;
            uint2 ph, pl;
            ph.x = pack2(h0, h1); ph.y = pack2(h2, h3);
            pl.x = pack2(l0, l1); pl.y = pack2(l2, l3);
            *reinterpret_cast<uint2*>(sAhi + so) = ph;
            *reinterpret_cast<uint2*>(sAlo + so) = pl;
        }
        // ---- stage B (in place; L2-hot after first wave) ----
#pragma unroll
        for (int i = 0; i < 2; i++) {
            int u = tid + i * 256;
            int row = u >> 2;
            int c = (u & 3) * 8;
            uint4 vh = *reinterpret_cast<const uint4*>(WH + (size_t)row * HID + koff + c);
            uint4 vl = *reinterpret_cast<const uint4*>(WL + (size_t)row * HID + koff + c);
            int so = row * TSTRIDE + c;
            *reinterpret_cast<uint4*>(sBhi + so) = vh;
            *reinterpret_cast<uint4*>(sBlo + so) = vl;
        }
        __syncthreads();

        // ---- prefetch next chunk's A while MMAs run ----
        if (chunk < 7) fetchA(chunk + 1);

#pragma unroll
        for (int ks = 0; ks < 2; ks++) {
            const int k0 = ks * 16;
            uint32_t ahi[2][4], alo[2][4];
#pragma unroll
            for (int mi = 0; mi < 2; mi++) {
                uint32_t off = ((arow + mi * 16) * TSTRIDE + k0 + akof) * 2;
                LDMX4(ahi[mi], uAhi + off);
                LDMX4(alo[mi], uAlo + off);
            }
#pragma unroll
            for (int np = 0; np < 4; np++) {
                uint32_t boff = ((nrow0 + np * 16) * TSTRIDE + k0 + nkof) * 2;
                uint32_t bh4[4], bl4[4];
                LDMX4(bh4, uBhi + boff);
                LDMX4(bl4, uBlo + boff);
#pragma unroll
                for (int mi = 0; mi < 2; mi++) {
#pragma unroll
                    for (int na = 0; na < 2; na++) {
                        float* c = acc[mi][np * 2 + na];
                        mma16816(c, ahi[mi], &bh4[na * 2]);
                        mma16816(c, ahi[mi], &bl4[na * 2]);
                        mma16816(c, alo[mi], &bh4[na * 2]);
                    }
                }
            }
        }
        __syncthreads();
    }

    if (!FINAL) {
#pragma unroll
        for (int mi = 0; mi < 2; mi++) {
            int row0 = m0 + wm * 32 + mi * 16 + (lane >> 2);
            int row1 = row0 + 8;
#pragma unroll
            for (int ni = 0; ni < 8; ni++) {
                int col = wn * 64 + ni * 8 + 2 * (lane & 3);
                float b0 = __ldg(bias + col);
                float b1 = __ldg(bias + col + 1);
                float* c = acc[mi][ni];
                if (row0 < M) {
                    float2 v;
                    v.x = fmaxf(c[0] + b0, 0.f);
                    v.y = fmaxf(c[1] + b1, 0.f);
                    *reinterpret_cast<float2*>(C + (size_t)row0 * HID + col) = v;
                }
                if (row1 < M) {
                    float2 v;
                    v.x = fmaxf(c[2] + b0, 0.f);
                    v.y = fmaxf(c[3] + b1, 0.f);
                    *reinterpret_cast<float2*>(C + (size_t)row1 * HID + col) = v;
                }
            }
        }
    } else {
#pragma unroll
        for (int mi = 0; mi < 2; mi++) {
            float p0[OUTDIM] = {0.f, 0.f, 0.f, 0.f};
            float p1[OUTDIM] = {0.f, 0.f, 0.f, 0.f};
#pragma unroll
            for (int ni = 0; ni < 8; ni++) {
                int col = wn * 64 + ni * 8 + 2 * (lane & 3);
                float b0 = __ldg(bias + col);
                float b1 = __ldg(bias + col + 1);
                float* c = acc[mi][ni];
                float v0 = fmaxf(c[0] + b0, 0.f);
                float v1 = fmaxf(c[1] + b1, 0.f);
                float v2 = fmaxf(c[2] + b0, 0.f);
                float v3 = fmaxf(c[3] + b1, 0.f);
#pragma unroll
                for (int j = 0; j < OUTDIM; j++) {
                    float w0 = sWh[j * HID + col];
                    float w1 = sWh[j * HID + col + 1];
                    p0[j] += v0 * w0 + v1 * w1;
                    p1[j] += v2 * w0 + v3 * w1;
                }
            }
#pragma unroll
            for (int j = 0; j < OUTDIM; j++) {
                p0[j] += __shfl_xor_sync(0xffffffffu, p0[j], 1);
                p0[j] += __shfl_xor_sync(0xffffffffu, p0[j], 2);
                p1[j] += __shfl_xor_sync(0xffffffffu, p1[j], 1);
                p1[j] += __shfl_xor_sync(0xffffffffu, p1[j], 2);
            }
            if ((lane & 3) == 0) {
                int r0 = wm * 32 + mi * 16 + (lane >> 2);
                int r1 = r0 + 8;
#pragma unroll
                for (int j = 0; j < OUTDIM; j++) {
                    red[r0 * 8 + j * 2 + wn] = p0[j];
                    red[r1 * 8 + j * 2 + wn] = p1[j];
                }
            }
        }
        __syncthreads();
        for (int u = tid; u < 128 * OUTDIM; u += 256) {
            int row = u >> 2;
            int j = u & 3;
            int node = m0 + row;
            if (node < M)
                out[(size_t)node * OUTDIM + j] =
                    red[row * 8 + j * 2 + 0] + red[row * 8 + j * 2 + 1] + sbh[j];
        }
    }
}

// ---------------------------------------------------------------
extern "C" void kernel_launch(void* const* d_in, const int* in_sizes, int n_in,
                              void* d_out, int out_size) {
    (void)n_in; (void)out_size;
    const float* x   = (const float*)d_in[0];
    const int*   ei  = (const int*)d_in[1];
    const float* Wl1 = (const float*)d_in[2];
    const float* Wr1 = (const float*)d_in[3];
    const float* b1  = (const float*)d_in[4];
    const float* Wl2 = (const float*)d_in[5];
    const float* Wr2 = (const float*)d_in[6];
    const float* b2  = (const float*)d_in[7];
    const float* Wl3 = (const float*)d_in[8];
    const float* Wr3 = (const float*)d_in[9];
    const float* b3  = (const float*)d_in[10];
    const float* Wh  = (const float*)d_in[11];
    const float* bh  = (const float*)d_in[12];
    float* out = (float*)d_out;

    const int M = in_sizes[0] / INDIM;   // 50000
    const int E = in_sizes[1] / 2;       // 600000

    float *agg, *hA, *hB;
    __nv_bfloat16 *wHi, *wLo;
    cudaGetSymbolAddress((void**)&agg, g_agg);
    cudaGetSymbolAddress((void**)&hA, g_hA);
    cudaGetSymbolAddress((void**)&hB, g_hB);
    cudaGetSymbolAddress((void**)&wHi, g_wHi);
    cudaGetSymbolAddress((void**)&wLo, g_wLo);

    const int T = 256;
    const int NB = (M + SCAN_CHUNK - 1) / SCAN_CHUNK;

    // ---- CSR build ----
    init_kernel<<<(M + T - 1) / T, T>>>(ei, M);
    convert_kernel<<<(E + T - 1) / T, T>>>(ei, E);
    scan_phase1<<<NB, 256>>>(M);
    scan_phase3<<<NB, 256>>>(M, E, NB);
    fill_kernel<<<(E + T - 1) / T, T>>>(E);

    // ---- weight splits (all 6 in one launch) ----
    wsplit_all_kernel<<<(WTOT + T - 1) / T, T>>>(Wl2, Wr2, Wl3, Wr3, Wl1, Wr1);

    const int gemmBlocks = (M + 127) / 128;

    // ---- layer 1 (16 -> 128), mma.sync ----
    gather16_kernel<<<((M * 4) + T - 1) / T, T>>>(x, agg, M);
    tensor_l1_kernel<<<gemmBlocks, 256>>>(agg, x, wHi + W1L_OFF, wLo + W1L_OFF, b1, hA, M);

    // ---- layer 2 (128 -> 128), mma.sync ----
    gather128_kernel<<<((M * 32) + T - 1) / T, T>>>(hA, agg, M);
    tensor_sage_kernel<false><<<gemmBlocks, 256>>>(agg, hA,
        wHi + W2L_OFF, wLo + W2L_OFF, wHi + W2R_OFF, wLo + W2R_OFF,
        b2, hB, nullptr, nullptr, nullptr, M);

    // ---- layer 3 (128 -> 128) + fused final projection ----
    gather128_kernel<<<((M * 32) + T - 1) / T, T>>>(hB, agg, M);
    tensor_sage_kernel<true><<<gemmBlocks, 256>>>(agg, hB,
        wHi + W3L_OFF, wLo + W3L_OFF, wHi + W3R_OFF, wLo + W3R_OFF,
        b3, nullptr, Wh, bh, out, M);
}

// round 17
// speedup vs baseline: 1.1097x; 1.0528x over previous
#include <cuda_runtime.h>
#include <cuda_bf16.h>
#include <cstdint>

#define NN 50000
#define HID 128
#define INDIM 16
#define OUTDIM 4
#define MAXE 600000
#define SCAN_CHUNK 1024
#define MAX_SCAN_BLOCKS 128
#define TSTRIDE 40   // smem tile row stride in bf16 elements (80B -> conflict-free ldmatrix)

// flat split-weight offsets (bf16 elems)
#define W2L_OFF 0
#define W2R_OFF 16384
#define W3L_OFF 32768
#define W3R_OFF 49152
#define W1L_OFF 65536
#define W1R_OFF 67584
#define WTOT    69632

// ---- scratch (static device globals; no runtime allocation) ----
// NOTE: g_deg relies on the zero-initialization of __device__ globals for the
// first run; scan_phase3 re-zeroes it after use so the invariant holds on
// every graph replay.
__device__ float g_agg[NN * HID];
__device__ float g_hA[NN * HID];
__device__ float g_hB[NN * HID];
__device__ __nv_bfloat16 g_wHi[WTOT];
__device__ __nv_bfloat16 g_wLo[WTOT];
__device__ int g_src[MAXE];
__device__ int g_dst[MAXE];
__device__ int g_csrc[MAXE];
__device__ int g_deg[NN];
__device__ int g_rowstart[NN + 1];
__device__ int g_cursor[NN];
__device__ int g_blocksum[MAX_SCAN_BLOCKS];
__device__ int g_is64;

// ================= helpers =================
__device__ __forceinline__ uint32_t smem_u32(const void* p) {
    uint32_t a;
    asm("{ .reg .u64 t; cvta.to.shared.u64 t, %1; cvt.u32.u64 %0, t; }" : "=r"(a) : "l"(p));
    return a;
}

#define LDMX4(r, a)                                                            \
    asm volatile("ldmatrix.sync.aligned.m8n8.x4.shared.b16 {%0,%1,%2,%3}, [%4];" \
                 : "=r"((r)[0]), "=r"((r)[1]), "=r"((r)[2]), "=r"((r)[3])      \
                 : "r"(a))

__device__ __forceinline__ void mma16816(float* c, const uint32_t* a, const uint32_t* b) {
    asm volatile(
        "mma.sync.aligned.m16n8k16.row.col.f32.bf16.bf16.f32 "
        "{%0,%1,%2,%3}, {%4,%5,%6,%7}, {%8,%9}, {%0,%1,%2,%3};"
        : "+f"(c[0]), "+f"(c[1]), "+f"(c[2]), "+f"(c[3])
        : "r"(a[0]), "r"(a[1]), "r"(a[2]), "r"(a[3]), "r"(b[0]), "r"(b[1]));
}

__device__ __forceinline__ void split2(float v, __nv_bfloat16& hi, __nv_bfloat16& lo) {
    hi = __float2bfloat16(v);
    lo = __float2bfloat16(v - __bfloat162float(hi));
}
__device__ __forceinline__ uint32_t pack2(__nv_bfloat16 a, __nv_bfloat16 b) {
    __nv_bfloat162 t = __halves2bfloat162(a, b);
    return *reinterpret_cast<uint32_t*>(&t);
}

// ================= CSR build =================
// dtype detect only (1 block): int64 edge ids < 2^31 have all-zero hi words
// at odd 32-bit positions.
__global__ void detect_kernel(const int* __restrict__ w) {
    __shared__ int anynz;
    if (threadIdx.x == 0) anynz = 0;
    __syncthreads();
    if (threadIdx.x < 64 && w[2 * threadIdx.x + 1] != 0) atomicOr(&anynz, 1);
    __syncthreads();
    if (threadIdx.x == 0) g_is64 = anynz ? 0 : 1;
}

// convert (edge blocks) + weight split (tail blocks) fused in one launch.
__global__ void convert_wsplit_kernel(const int* __restrict__ w, int E, int EB,
                                      const float* __restrict__ Wl2, const float* __restrict__ Wr2,
                                      const float* __restrict__ Wl3, const float* __restrict__ Wr3,
                                      const float* __restrict__ Wl1, const float* __restrict__ Wr1) {
    if (blockIdx.x < (unsigned)EB) {
        int i = blockIdx.x * blockDim.x + threadIdx.x;
        if (i >= E) return;
        int s, d;
        if (g_is64) { s = w[2 * i]; d = w[2 * (E + i)]; }
        else        { s = w[i];     d = w[E + i];       }
        g_src[i] = s;
        g_dst[i] = d;
        atomicAdd(&g_deg[d], 1);
    } else {
        int i = (blockIdx.x - EB) * blockDim.x + threadIdx.x;
        if (i >= WTOT) return;
        const float* src;
        int off;
        if (i < W2R_OFF)      { src = Wl2; off = i - W2L_OFF; }
        else if (i < W3L_OFF) { src = Wr2; off = i - W2R_OFF; }
        else if (i < W3R_OFF) { src = Wl3; off = i - W3L_OFF; }
        else if (i < W1L_OFF) { src = Wr3; off = i - W3R_OFF; }
        else if (i < W1R_OFF) { src = Wl1; off = i - W1L_OFF; }
        else                  { src = Wr1; off = i - W1R_OFF; }
        __nv_bfloat16 h, l;
        split2(src[off], h, l);
        g_wHi[i] = h;
        g_wLo[i] = l;
    }
}

__device__ __forceinline__ void block_scan_1024(int& thread_sum, int& thread_excl, int* warp_buf) {
    int t = threadIdx.x;
    int lane = t & 31, w = t >> 5;
    int v = thread_sum;
#pragma unroll
    for (int off = 1; off < 32; off <<= 1) {
        int u = __shfl_up_sync(0xffffffffu, v, off);
        if (lane >= off) v += u;
    }
    if (lane == 31) warp_buf[w] = v;
    __syncthreads();
    if (w == 0) {
        int ws = (lane < 8) ? warp_buf[lane] : 0;
#pragma unroll
        for (int off = 1; off < 8; off <<= 1) {
            int u = __shfl_up_sync(0xffffffffu, ws, off);
            if (lane >= off) ws += u;
        }
        if (lane < 8) warp_buf[lane] = ws;
    }
    __syncthreads();
    thread_excl = v - thread_sum + (w > 0 ? warp_buf[w - 1] : 0);
}

__global__ void scan_phase1(int M) {
    __shared__ int warp_buf[8];
    int b = blockIdx.x, t = threadIdx.x;
    int base = b * SCAN_CHUNK + t * 4;
    int d[4] = {0, 0, 0, 0};
#pragma unroll
    for (int i = 0; i < 4; i++)
        if (base + i < M) d[i] = g_deg[base + i];
    int s = d[0] + d[1] + d[2] + d[3];
    int excl;
    block_scan_1024(s, excl, warp_buf);
    if (t == blockDim.x - 1) g_blocksum[b] = excl + s;
}

// phase2 folded in; also zeroes g_deg after use (replay invariant).
__global__ void scan_phase3(int M, int E, int NB) {
    __shared__ int warp_buf[8];
    __shared__ int bsum[MAX_SCAN_BLOCKS];
    __shared__ int boff;
    int b = blockIdx.x, t = threadIdx.x;
    if (t < NB) bsum[t] = g_blocksum[t];
    __syncthreads();
    if (t == 0) {
        int run = 0;
        for (int i = 0; i < b; i++) run += bsum[i];
        boff = run;
    }
    int base = b * SCAN_CHUNK + t * 4;
    int d[4] = {0, 0, 0, 0};
#pragma unroll
    for (int i = 0; i < 4; i++)
        if (base + i < M) d[i] = g_deg[base + i];
    int s = d[0] + d[1] + d[2] + d[3];
    int excl;
    block_scan_1024(s, excl, warp_buf);
    __syncthreads();
    int run = excl + boff;
#pragma unroll
    for (int i = 0; i < 4; i++) {
        if (base + i < M) {
            g_rowstart[base + i] = run;
            g_cursor[base + i] = run;
            g_deg[base + i] = 0;   // reset for next replay
            run += d[i];
        }
    }
    if (b == 0 && t == 0) g_rowstart[M] = E;
}

__global__ void fill_kernel(int E) {
    int i = blockIdx.x * blockDim.x + threadIdx.x;
    if (i >= E) return;
    int d = g_dst[i];
    int pos = atomicAdd(&g_cursor[d], 1);
    g_csrc[pos] = g_src[i];
}

// ================= gathers (fp32, CSR) — proven R9 form =================
__global__ void gather128_kernel(const float* __restrict__ h, float* __restrict__ agg, int M) {
    int gt = blockIdx.x * blockDim.x + threadIdx.x;
    int n = gt >> 5;
    if (n >= M) return;
    int lane = gt & 31;
    int rs0 = g_rowstart[n], rs1 = g_rowstart[n + 1];
    float4 acc = make_float4(0.f, 0.f, 0.f, 0.f);
    int i = rs0;
    for (; i + 4 <= rs1; i += 4) {
        int s0 = g_csrc[i + 0];
        int s1 = g_csrc[i + 1];
        int s2 = g_csrc[i + 2];
        int s3 = g_csrc[i + 3];
        float4 v0 = __ldg(reinterpret_cast<const float4*>(h + (size_t)s0 * HID) + lane);
        float4 v1 = __ldg(reinterpret_cast<const float4*>(h + (size_t)s1 * HID) + lane);
        float4 v2 = __ldg(reinterpret_cast<const float4*>(h + (size_t)s2 * HID) + lane);
        float4 v3 = __ldg(reinterpret_cast<const float4*>(h + (size_t)s3 * HID) + lane);
        acc.x += v0.x + v1.x + v2.x + v3.x;
        acc.y += v0.y + v1.y + v2.y + v3.y;
        acc.z += v0.z + v1.z + v2.z + v3.z;
        acc.w += v0.w + v1.w + v2.w + v3.w;
    }
    for (; i < rs1; i++) {
        int s0 = g_csrc[i];
        float4 v0 = __ldg(reinterpret_cast<const float4*>(h + (size_t)s0 * HID) + lane);
        acc.x += v0.x; acc.y += v0.y; acc.z += v0.z; acc.w += v0.w;
    }
    float sc = 1.0f / (float)max(rs1 - rs0, 1);
    acc.x *= sc; acc.y *= sc; acc.z *= sc; acc.w *= sc;
    reinterpret_cast<float4*>(agg + (size_t)n * HID)[lane] = acc;
}

__global__ void gather16_kernel(const float* __restrict__ x, float* __restrict__ agg, int M) {
    int gt = blockIdx.x * blockDim.x + threadIdx.x;
    int n = gt >> 2;
    if (n >= M) return;
    int q = gt & 3;
    int rs0 = g_rowstart[n], rs1 = g_rowstart[n + 1];
    float4 acc = make_float4(0.f, 0.f, 0.f, 0.f);
    for (int i = rs0; i < rs1; i++) {
        int s0 = g_csrc[i];
        float4 v = __ldg(reinterpret_cast<const float4*>(x + (size_t)s0 * INDIM) + q);
        acc.x += v.x; acc.y += v.y; acc.z += v.z; acc.w += v.w;
    }
    float sc = 1.0f / (float)max(rs1 - rs0, 1);
    acc.x *= sc; acc.y *= sc; acc.z *= sc; acc.w *= sc;
    reinterpret_cast<float4*>(agg + (size_t)n * INDIM)[q] = acc;
}

// ================= layer-1 tensor GEMM (K=32) via mma.sync =================
__global__ void __launch_bounds__(256)
tensor_l1_kernel(const float* __restrict__ agg, const float* __restrict__ x,
                 const __nv_bfloat16* __restrict__ WHi, const __nv_bfloat16* __restrict__ WLo,
                 const float* __restrict__ bias, float* __restrict__ C, int M) {
    __shared__ __nv_bfloat16 sAhi[128 * TSTRIDE];
    __shared__ __nv_bfloat16 sAlo[128 * TSTRIDE];
    __shared__ __nv_bfloat16 sBhi[128 * TSTRIDE];
    __shared__ __nv_bfloat16 sBlo[128 * TSTRIDE];

    const int tid = threadIdx.x;
    const int wid = tid >> 5;
    const int lane = tid & 31;
    const int wm = wid & 3;
    const int wn = wid >> 2;
    const int m0 = blockIdx.x * 128;

    {
        int row = tid >> 1;
        int half = tid & 1;
        const float* src = half ? x : agg;
        int node = m0 + row;
        float4 v[4];
#pragma unroll
        for (int i = 0; i < 4; i++) v[i] = make_float4(0.f, 0.f, 0.f, 0.f);
        if (node < M) {
            const float4* p = reinterpret_cast<const float4*>(src + (size_t)node * INDIM);
#pragma unroll
            for (int i = 0; i < 4; i++) v[i] = p[i];
        }
        int so = row * TSTRIDE + half * 16;
#pragma unroll
        for (int i = 0; i < 4; i++) {
            __nv_bfloat16 h0, l0, h1, l1, h2, l2, h3, l3;
            split2(v[i].x, h0, l0);
            split2(v[i].y, h1, l1);
            split2(v[i].z, h2, l2);
            split2(v[i].w, h3, l3);
            uint2 ph, pl;
            ph.x = pack2(h0, h1); ph.y = pack2(h2, h3);
            pl.x = pack2(l0, l1); pl.y = pack2(l2, l3);
            *reinterpret_cast<uint2*>(sAhi + so + i * 4) = ph;
            *reinterpret_cast<uint2*>(sAlo + so + i * 4) = pl;
        }
    }
    {
        int row = tid >> 1;
        int half = tid & 1;
        const __nv_bfloat16* WH = WHi + half * 2048;
        const __nv_bfloat16* WL = WLo + half * 2048;
        int so = row * TSTRIDE + half * 16;
        uint4 h0 = *reinterpret_cast<const uint4*>(WH + row * 16);
        uint4 h1 = *reinterpret_cast<const uint4*>(WH + row * 16 + 8);
        uint4 l0 = *reinterpret_cast<const uint4*>(WL + row * 16);
        uint4 l1 = *reinterpret_cast<const uint4*>(WL + row * 16 + 8);
        *reinterpret_cast<uint4*>(sBhi + so) = h0;
        *reinterpret_cast<uint4*>(sBhi + so + 8) = h1;
        *reinterpret_cast<uint4*>(sBlo + so) = l0;
        *reinterpret_cast<uint4*>(sBlo + so + 8) = l1;
    }
    __syncthreads();

    const uint32_t uAhi = smem_u32(sAhi);
    const uint32_t uAlo = smem_u32(sAlo);
    const uint32_t uBhi = smem_u32(sBhi);
    const uint32_t uBlo = smem_u32(sBlo);

    float acc[2][8][4];
#pragma unroll
    for (int i = 0; i < 2; i++)
#pragma unroll
        for (int j = 0; j < 8; j++)
#pragma unroll
            for (int k = 0; k < 4; k++) acc[i][j][k] = 0.f;

    const int arow = wm * 32 + (lane & 15);
    const int akof = (lane & 16) ? 8 : 0;
    const int nrow0 = wn * 64 + (lane & 7) + ((lane & 16) ? 8 : 0);
    const int nkof = (lane & 8) ? 8 : 0;

#pragma unroll
    for (int ks = 0; ks < 2; ks++) {
        const int k0 = ks * 16;
        uint32_t ahi[2][4], alo[2][4];
#pragma unroll
        for (int mi = 0; mi < 2; mi++) {
            uint32_t off = ((arow + mi * 16) * TSTRIDE + k0 + akof) * 2;
            LDMX4(ahi[mi], uAhi + off);
            LDMX4(alo[mi], uAlo + off);
        }
#pragma unroll
        for (int np = 0; np < 4; np++) {
            uint32_t boff = ((nrow0 + np * 16) * TSTRIDE + k0 + nkof) * 2;
            uint32_t bh4[4], bl4[4];
            LDMX4(bh4, uBhi + boff);
            LDMX4(bl4, uBlo + boff);
#pragma unroll
            for (int mi = 0; mi < 2; mi++) {
#pragma unroll
                for (int na = 0; na < 2; na++) {
                    float* c = acc[mi][np * 2 + na];
                    mma16816(c, ahi[mi], &bh4[na * 2]);
                    mma16816(c, ahi[mi], &bl4[na * 2]);
                    mma16816(c, alo[mi], &bh4[na * 2]);
                }
            }
        }
    }

#pragma unroll
    for (int mi = 0; mi < 2; mi++) {
        int row0 = m0 + wm * 32 + mi * 16 + (lane >> 2);
        int row1 = row0 + 8;
#pragma unroll
        for (int ni = 0; ni < 8; ni++) {
            int col = wn * 64 + ni * 8 + 2 * (lane & 3);
            float b0 = __ldg(bias + col);
            float b1 = __ldg(bias + col + 1);
            float* c = acc[mi][ni];
            if (row0 < M) {
                float2 v;
                v.x = fmaxf(c[0] + b0, 0.f);
                v.y = fmaxf(c[1] + b1, 0.f);
                *reinterpret_cast<float2*>(C + (size_t)row0 * HID + col) = v;
            }
            if (row1 < M) {
                float2 v;
                v.x = fmaxf(c[2] + b0, 0.f);
                v.y = fmaxf(c[3] + b1, 0.f);
                *reinterpret_cast<float2*>(C + (size_t)row1 * HID + col) = v;
            }
        }
    }
}

// ================= tensor-core SAGE GEMM (layers 2/3) via mma.sync =================
template <bool FINAL>
__global__ void __launch_bounds__(256)
tensor_sage_kernel(const float* __restrict__ A0, const float* __restrict__ A1,
                   const __nv_bfloat16* __restrict__ W0hi, const __nv_bfloat16* __restrict__ W0lo,
                   const __nv_bfloat16* __restrict__ W1hi, const __nv_bfloat16* __restrict__ W1lo,
                   const float* __restrict__ bias, float* __restrict__ C,
                   const float* __restrict__ Wh, const float* __restrict__ bh,
                   float* __restrict__ out, int M) {
    __shared__ __nv_bfloat16 sAhi[128 * TSTRIDE];
    __shared__ __nv_bfloat16 sAlo[128 * TSTRIDE];
    __shared__ __nv_bfloat16 sBhi[128 * TSTRIDE];
    __shared__ __nv_bfloat16 sBlo[128 * TSTRIDE];
    __shared__ float sWh[OUTDIM * HID];
    __shared__ float sbh[OUTDIM];
    __shared__ float red[128 * 8];

    const int tid = threadIdx.x;
    const int wid = tid >> 5;
    const int lane = tid & 31;
    const int wm = wid & 3;
    const int wn = wid >> 2;
    const int m0 = blockIdx.x * 128;

    if (FINAL) {
        for (int u = tid; u < OUTDIM * HID; u += 256) sWh[u] = Wh[u];
        if (tid < OUTDIM) sbh[tid] = bh[tid];
    }

    const uint32_t uAhi = smem_u32(sAhi);
    const uint32_t uAlo = smem_u32(sAlo);
    const uint32_t uBhi = smem_u32(sBhi);
    const uint32_t uBlo = smem_u32(sBlo);

    float acc[2][8][4];
#pragma unroll
    for (int i = 0; i < 2; i++)
#pragma unroll
        for (int j = 0; j < 8; j++)
#pragma unroll
            for (int k = 0; k < 4; k++) acc[i][j][k] = 0.f;

    const int arow = wm * 32 + (lane & 15);
    const int akof = (lane & 16) ? 8 : 0;
    const int nrow0 = wn * 64 + (lane & 7) + ((lane & 16) ? 8 : 0);
    const int nkof = (lane & 8) ? 8 : 0;

#pragma unroll
    for (int chunk = 0; chunk < 8; chunk++) {
        const float* A = (chunk < 4) ? A0 : A1;
        const __nv_bfloat16* WH = (chunk < 4) ? W0hi : W1hi;
        const __nv_bfloat16* WL = (chunk < 4) ? W0lo : W1lo;
        const int koff = (chunk & 3) * 32;

        __syncthreads();
#pragma unroll
        for (int i = 0; i < 4; i++) {
            int u = tid + i * 256;
            int row = u >> 3;
            int q = (u & 7) * 4;
            float4 v = make_float4(0.f, 0.f, 0.f, 0.f);
            int node = m0 + row;
            if (node < M)
                v = *reinterpret_cast<const float4*>(A + (size_t)node * HID + koff + q);
            __nv_bfloat16 h0, l0, h1, l1, h2, l2, h3, l3;
            split2(v.x, h0, l0);
            split2(v.y, h1, l1);
            split2(v.z, h2, l2);
            split2(v.w, h3, l3);
            int so = row * TSTRIDE + q;
            uint2 ph, pl;
            ph.x = pack2(h0, h1); ph.y = pack2(h2, h3);
            pl.x = pack2(l0, l1); pl.y = pack2(l2, l3);
            *reinterpret_cast<uint2*>(sAhi + so) = ph;
            *reinterpret_cast<uint2*>(sAlo + so) = pl;
        }
#pragma unroll
        for (int i = 0; i < 2; i++) {
            int u = tid + i * 256;
            int row = u >> 2;
            int c = (u & 3) * 8;
            uint4 vh = *reinterpret_cast<const uint4*>(WH + (size_t)row * HID + koff + c);
            uint4 vl = *reinterpret_cast<const uint4*>(WL + (size_t)row * HID + koff + c);
            int so = row * TSTRIDE + c;
            *reinterpret_cast<uint4*>(sBhi + so) = vh;
            *reinterpret_cast<uint4*>(sBlo + so) = vl;
        }
        __syncthreads();

#pragma unroll
        for (int ks = 0; ks < 2; ks++) {
            const int k0 = ks * 16;
            uint32_t ahi[2][4], alo[2][4];
#pragma unroll
            for (int mi = 0; mi < 2; mi++) {
                uint32_t off = ((arow + mi * 16) * TSTRIDE + k0 + akof) * 2;
                LDMX4(ahi[mi], uAhi + off);
                LDMX4(alo[mi], uAlo + off);
            }
#pragma unroll
            for (int np = 0; np < 4; np++) {
                uint32_t boff = ((nrow0 + np * 16) * TSTRIDE + k0 + nkof) * 2;
                uint32_t bh4[4], bl4[4];
                LDMX4(bh4, uBhi + boff);
                LDMX4(bl4, uBlo + boff);
#pragma unroll
                for (int mi = 0; mi < 2; mi++) {
#pragma unroll
                    for (int na = 0; na < 2; na++) {
                        float* c = acc[mi][np * 2 + na];
                        mma16816(c, ahi[mi], &bh4[na * 2]);
                        mma16816(c, ahi[mi], &bl4[na * 2]);
                        mma16816(c, alo[mi], &bh4[na * 2]);
                    }
                }
            }
        }
    }

    if (!FINAL) {
#pragma unroll
        for (int mi = 0; mi < 2; mi++) {
            int row0 = m0 + wm * 32 + mi * 16 + (lane >> 2);
            int row1 = row0 + 8;
#pragma unroll
            for (int ni = 0; ni < 8; ni++) {
                int col = wn * 64 + ni * 8 + 2 * (lane & 3);
                float b0 = __ldg(bias + col);
                float b1 = __ldg(bias + col + 1);
                float* c = acc[mi][ni];
                if (row0 < M) {
                    float2 v;
                    v.x = fmaxf(c[0] + b0, 0.f);
                    v.y = fmaxf(c[1] + b1, 0.f);
                    *reinterpret_cast<float2*>(C + (size_t)row0 * HID + col) = v;
                }
                if (row1 < M) {
                    float2 v;
                    v.x = fmaxf(c[2] + b0, 0.f);
                    v.y = fmaxf(c[3] + b1, 0.f);
                    *reinterpret_cast<float2*>(C + (size_t)row1 * HID + col) = v;
                }
            }
        }
    } else {
#pragma unroll
        for (int mi = 0; mi < 2; mi++) {
            float p0[OUTDIM] = {0.f, 0.f, 0.f, 0.f};
            float p1[OUTDIM] = {0.f, 0.f, 0.f, 0.f};
#pragma unroll
            for (int ni = 0; ni < 8; ni++) {
                int col = wn * 64 + ni * 8 + 2 * (lane & 3);
                float b0 = __ldg(bias + col);
                float b1 = __ldg(bias + col + 1);
                float* c = acc[mi][ni];
                float v0 = fmaxf(c[0] + b0, 0.f);
                float v1 = fmaxf(c[1] + b1, 0.f);
                float v2 = fmaxf(c[2] + b0, 0.f);
                float v3 = fmaxf(c[3] + b1, 0.f);
#pragma unroll
                for (int j = 0; j < OUTDIM; j++) {
                    float w0 = sWh[j * HID + col];
                    float w1 = sWh[j * HID + col + 1];
                    p0[j] += v0 * w0 + v1 * w1;
                    p1[j] += v2 * w0 + v3 * w1;
                }
            }
#pragma unroll
            for (int j = 0; j < OUTDIM; j++) {
                p0[j] += __shfl_xor_sync(0xffffffffu, p0[j], 1);
                p0[j] += __shfl_xor_sync(0xffffffffu, p0[j], 2);
                p1[j] += __shfl_xor_sync(0xffffffffu, p1[j], 1);
                p1[j] += __shfl_xor_sync(0xffffffffu, p1[j], 2);
            }
            if ((lane & 3) == 0) {
                int r0 = wm * 32 + mi * 16 + (lane >> 2);
                int r1 = r0 + 8;
#pragma unroll
                for (int j = 0; j < OUTDIM; j++) {
                    red[r0 * 8 + j * 2 + wn] = p0[j];
                    red[r1 * 8 + j * 2 + wn] = p1[j];
                }
            }
        }
        __syncthreads();
        for (int u = tid; u < 128 * OUTDIM; u += 256) {
            int row = u >> 2;
            int j = u & 3;
            int node = m0 + row;
            if (node < M)
                out[(size_t)node * OUTDIM + j] =
                    red[row * 8 + j * 2 + 0] + red[row * 8 + j * 2 + 1] + sbh[j];
        }
    }
}

// ---------------------------------------------------------------
extern "C" void kernel_launch(void* const* d_in, const int* in_sizes, int n_in,
                              void* d_out, int out_size) {
    (void)n_in; (void)out_size;
    const float* x   = (const float*)d_in[0];
    const int*   ei  = (const int*)d_in[1];
    const float* Wl1 = (const float*)d_in[2];
    const float* Wr1 = (const float*)d_in[3];
    const float* b1  = (const float*)d_in[4];
    const float* Wl2 = (const float*)d_in[5];
    const float* Wr2 = (const float*)d_in[6];
    const float* b2  = (const float*)d_in[7];
    const float* Wl3 = (const float*)d_in[8];
    const float* Wr3 = (const float*)d_in[9];
    const float* b3  = (const float*)d_in[10];
    const float* Wh  = (const float*)d_in[11];
    const float* bh  = (const float*)d_in[12];
    float* out = (float*)d_out;

    const int M = in_sizes[0] / INDIM;   // 50000
    const int E = in_sizes[1] / 2;       // 600000

    float *agg, *hA, *hB;
    __nv_bfloat16 *wHi, *wLo;
    cudaGetSymbolAddress((void**)&agg, g_agg);
    cudaGetSymbolAddress((void**)&hA, g_hA);
    cudaGetSymbolAddress((void**)&hB, g_hB);
    cudaGetSymbolAddress((void**)&wHi, g_wHi);
    cudaGetSymbolAddress((void**)&wLo, g_wLo);

    const int T = 256;
    const int NB = (M + SCAN_CHUNK - 1) / SCAN_CHUNK;
    const int EB = (E + T - 1) / T;
    const int WB = (WTOT + T - 1) / T;

    // ---- CSR build (+fused weight split) ----
    detect_kernel<<<1, 64>>>(ei);
    convert_wsplit_kernel<<<EB + WB, T>>>(ei, E, EB, Wl2, Wr2, Wl3, Wr3, Wl1, Wr1);
    scan_phase1<<<NB, 256>>>(M);
    scan_phase3<<<NB, 256>>>(M, E, NB);
    fill_kernel<<<EB, T>>>(E);

    const int gemmBlocks = (M + 127) / 128;

    // ---- layer 1 (16 -> 128), mma.sync ----
    gather16_kernel<<<((M * 4) + T - 1) / T, T>>>(x, agg, M);
    tensor_l1_kernel<<<gemmBlocks, 256>>>(agg, x, wHi + W1L_OFF, wLo + W1L_OFF, b1, hA, M);

    // ---- layer 2 (128 -> 128), mma.sync ----
    gather128_kernel<<<((M * 32) + T - 1) / T, T>>>(hA, agg, M);
    tensor_sage_kernel<false><<<gemmBlocks, 256>>>(agg, hA,
        wHi + W2L_OFF, wLo + W2L_OFF, wHi + W2R_OFF, wLo + W2R_OFF,
        b2, hB, nullptr, nullptr, nullptr, M);

    // ---- layer 3 (128 -> 128) + fused final projection ----
    gather128_kernel<<<((M * 32) + T - 1) / T, T>>>(hB, agg, M);
    tensor_sage_kernel<true><<<gemmBlocks, 256>>>(agg, hB,
        wHi + W3L_OFF, wLo + W3L_OFF, wHi + W3R_OFF, wLo + W3R_OFF,
        b3, nullptr, Wh, bh, out, M);
}